// round 10
// baseline (speedup 1.0000x reference)
#include <cuda_runtime.h>
#include <math.h>

typedef unsigned long long ull;

// ---------------------------------------------------------------------------
// Net_47132971107101: fake-quant CNN forward
//   conv1 fp32 (packed f32x2 FMA, streamed weights, no spills) -> 2-bit a1
//   conv2 dp4a (2 channels/thread, 98 lanes) -> 2-bit a2
//   FC dp4a -> out * 2*sf
// 2 images per 256-thread block.
// ---------------------------------------------------------------------------

__device__ ull   g_w1d[36];     // 4 outch x 9 taps, (w,w) packed f32x2, w = ternary*s1*0.5
__device__ int   g_w2pack[36];  // 4 outch x 9 taps, 4 in-ch int8 per word
__device__ __align__(16) int g_wfpack[492]; // 10 outs x 49 words (+pad)
__device__ float g_s2v;
__device__ float g_sf2;

__global__ void prep_kernel(const float* __restrict__ w1,
                            const float* __restrict__ w2,
                            const float* __restrict__ wf) {
    __shared__ float red[256];
    const int t = threadIdx.x;

    float m = 0.f;
    for (int i = t; i < 36; i += 256) m = fmaxf(m, fabsf(w1[i]));
    red[t] = m; __syncthreads();
    for (int s = 128; s > 0; s >>= 1) { if (t < s) red[t] = fmaxf(red[t], red[t+s]); __syncthreads(); }
    const float s1 = red[0]; __syncthreads();

    m = 0.f;
    for (int i = t; i < 144; i += 256) m = fmaxf(m, fabsf(w2[i]));
    red[t] = m; __syncthreads();
    for (int s = 128; s > 0; s >>= 1) { if (t < s) red[t] = fmaxf(red[t], red[t+s]); __syncthreads(); }
    const float s2 = red[0]; __syncthreads();

    m = 0.f;
    for (int i = t; i < 1960; i += 256) m = fmaxf(m, fabsf(wf[i]));
    red[t] = m; __syncthreads();
    for (int s = 128; s > 0; s >>= 1) { if (t < s) red[t] = fmaxf(red[t], red[t+s]); __syncthreads(); }
    const float sf = red[0];

    if (t < 36) {
        float q = fminf(fmaxf(rintf(w1[t] / s1), -1.f), 1.f);
        float w = 0.5f * s1 * q;
        unsigned int u; memcpy(&u, &w, 4);
        g_w1d[t] = ((ull)u << 32) | (ull)u;   // (w,w) f32x2 pair
    }
    if (t < 36) {
        const int o = t / 9, tap = t % 9;
        int pack = 0;
        #pragma unroll
        for (int i = 0; i < 4; i++) {
            float q = fminf(fmaxf(rintf(w2[o*36 + i*9 + tap] / s2), -1.f), 1.f);
            pack |= (((int)q) & 0xFF) << (8 * i);
        }
        g_w2pack[t] = pack;
    }
    for (int i = t; i < 490; i += 256) {
        const int o = i / 49, pp = i % 49;
        int pack = 0;
        #pragma unroll
        for (int j = 0; j < 4; j++) {
            float q = fminf(fmaxf(rintf(wf[o*196 + j*49 + pp] / sf), -1.f), 1.f);
            pack |= (((int)q) & 0xFF) << (8 * j);
        }
        g_wfpack[i] = pack;
    }
    if (t < 2) g_wfpack[490 + t] = 0;
    if (t == 0) { g_s2v = s2; g_sf2 = 2.f * sf; }
}

// ---- Blackwell packed f32x2 helpers --------------------------------------
__device__ __forceinline__ ull f2pk(float lo, float hi) {
    ull r; asm("mov.b64 %0, {%1,%2};" : "=l"(r) : "f"(lo), "f"(hi)); return r;
}
__device__ __forceinline__ void f2up(ull v, float& lo, float& hi) {
    asm("mov.b64 {%0,%1}, %2;" : "=f"(lo), "=f"(hi) : "l"(v));
}
__device__ __forceinline__ ull ffma2(ull a, ull b, ull c) {
    ull d; asm("fma.rn.f32x2 %0, %1, %2, %3;" : "=l"(d) : "l"(a), "l"(b), "l"(c)); return d;
}

#define TPB 256

__global__ void __launch_bounds__(TPB, 4)
net_kernel(const float* __restrict__ x, float* __restrict__ out) {
    __shared__ __align__(16) float img[2][30 * 34];  // zero-border padded
    __shared__ __align__(16) int   a1p[2][16 * 16];  // padded 14x14, 4ch bytes packed
    __shared__ __align__(16) int   a2w[2][52];       // 49 words: 4ch bytes @ spatial pp
    __shared__ __align__(16) ull   s_w1[36];         // prepacked (w,w) conv1 weights

    const int t = threadIdx.x;
    const int g = t >> 7;        // image within block
    const int u = t & 127;       // lane within image group
    const long long b0 = (long long)blockIdx.x * 2;

    // ---- phase 0: borders + weights + image interior ---------------------
    if (t < 36) s_w1[t] = g_w1d[t];
    if (t < 232) {               // img borders: 116 cells per image
        int gi = t / 116, j = t % 116, y, c;
        if (j < 30)      { y = 0;          c = j; }
        else if (j < 60) { y = 29;         c = j - 30; }
        else if (j < 88) { y = j - 60 + 1; c = 0; }
        else             { y = j - 88 + 1; c = 29; }
        img[gi][y * 34 + c] = 0.f;
    }
    if (t < 120) {               // a1p borders: 60 cells per image
        int gi = t / 60, j = t % 60, y, c;
        if (j < 16)      { y = 0;          c = j; }
        else if (j < 32) { y = 15;         c = j - 16; }
        else if (j < 46) { y = j - 32 + 1; c = 0; }
        else             { y = j - 46 + 1; c = 15; }
        a1p[gi][y * 16 + c] = 0;
    }
    if (t < 6) a2w[t / 3][49 + (t % 3)] = 0;  // pad for int4 FC reads

    for (int i = t; i < 392; i += TPB) {      // 196 float4 per image
        int gi = i / 196, q = i % 196;
        float4 v = ((const float4*)(x + (b0 + gi) * 784))[q];
        int p = q * 4, y = p / 28, c = p % 28;
        float* d = &img[gi][(y + 1) * 34 + (c + 1)];
        d[0] = v.x; d[1] = v.y; d[2] = v.z; d[3] = v.w;
    }
    __syncthreads();

    // ---- conv1 + pool + quant: thread -> (py, px-pair), all 4 channels ----
    if (u < 98) {
        const int py = u / 7, pxp = u % 7;
        const float* base = &img[g][(2 * py) * 34 + 4 * pxp];
        float2 pr[4][3];
        #pragma unroll
        for (int r = 0; r < 4; r++)
            #pragma unroll
            for (int j = 0; j < 3; j++)
                pr[r][j] = *(const float2*)(base + r * 34 + 2 * j);

        ull P0[4], P1[4], P2[4], X1[4], X2[4];
        #pragma unroll
        for (int r = 0; r < 4; r++) {
            P0[r] = f2pk(pr[r][0].x, pr[r][0].y);
            P1[r] = f2pk(pr[r][1].x, pr[r][1].y);
            P2[r] = f2pk(pr[r][2].x, pr[r][2].y);
            X1[r] = f2pk(pr[r][0].y, pr[r][1].x);
            X2[r] = f2pk(pr[r][1].y, pr[r][2].x);
        }

        int pk0 = 0, pk1 = 0;
        #pragma unroll
        for (int ch = 0; ch < 4; ch++) {
            const ull* wch = &s_w1[ch * 9];
            ull aA0 = 0ull, aA1 = 0ull, aB0 = 0ull, aB1 = 0ull;
            #pragma unroll
            for (int ky = 0; ky < 3; ky++) {
                const ull w0 = wch[ky*3 + 0];   // broadcast LDS.64
                const ull w1 = wch[ky*3 + 1];
                const ull w2 = wch[ky*3 + 2];
                aA0 = ffma2(P0[ky],     w0, aA0);
                aA0 = ffma2(X1[ky],     w1, aA0);
                aA0 = ffma2(P1[ky],     w2, aA0);
                aA1 = ffma2(P0[ky + 1], w0, aA1);
                aA1 = ffma2(X1[ky + 1], w1, aA1);
                aA1 = ffma2(P1[ky + 1], w2, aA1);
                aB0 = ffma2(P1[ky],     w0, aB0);
                aB0 = ffma2(X2[ky],     w1, aB0);
                aB0 = ffma2(P2[ky],     w2, aB0);
                aB1 = ffma2(P1[ky + 1], w0, aB1);
                aB1 = ffma2(X2[ky + 1], w1, aB1);
                aB1 = ffma2(P2[ky + 1], w2, aB1);
            }
            float l0, h0, l1, h1;
            f2up(aA0, l0, h0); f2up(aA1, l1, h1);
            const float m0 = fmaxf(fmaxf(l0, h0), fmaxf(l1, h1));
            f2up(aB0, l0, h0); f2up(aB1, l1, h1);
            const float m1 = fmaxf(fmaxf(l0, h0), fmaxf(l1, h1));
            const int a0 = min(max(__float2int_rn(m0), 0), 3);
            const int a1v = min(max(__float2int_rn(m1), 0), 3);
            pk0 |= a0 << (8 * ch);
            pk1 |= a1v << (8 * ch);
        }
        const int col = 2 * pxp + 1;
        a1p[g][(py + 1) * 16 + col]     = pk0;
        a1p[g][(py + 1) * 16 + col + 1] = pk1;
    }
    __syncthreads();

    // ---- conv2 + pool + quant: thread -> (spatial pp, 2 channels) ---------
    if (u < 98) {
        const int cp = (u >= 49) ? 1 : 0;     // channel pair: 0 -> ch0,1 ; 1 -> ch2,3
        const int pp = u - cp * 49;
        const int py = pp / 7, px = pp % 7;
        int q[4][4];
        #pragma unroll
        for (int r = 0; r < 4; r++) {
            int2 v0 = *(const int2*)&a1p[g][(2 * py + r) * 16 + 2 * px];
            int2 v1 = *(const int2*)&a1p[g][(2 * py + r) * 16 + 2 * px + 2];
            q[r][0] = v0.x; q[r][1] = v0.y; q[r][2] = v1.x; q[r][3] = v1.y;
        }
        const float s2v = g_s2v;
        unsigned int hv = 0;
        #pragma unroll
        for (int c2 = 0; c2 < 2; c2++) {
            const int ch = cp * 2 + c2;
            int wv[9];
            #pragma unroll
            for (int k = 0; k < 9; k++) wv[k] = __ldg(&g_w2pack[ch * 9 + k]);
            int mx = -2147483647;
            #pragma unroll
            for (int wy = 0; wy < 2; wy++)
                #pragma unroll
                for (int wx = 0; wx < 2; wx++) {
                    int acc = 0;
                    #pragma unroll
                    for (int ky = 0; ky < 3; ky++)
                        #pragma unroll
                        for (int kx = 0; kx < 3; kx++)
                            acc = __dp4a(q[wy + ky][wx + kx], wv[ky * 3 + kx], acc);
                    mx = max(mx, acc);
                }
            const int a = min(max(__float2int_rn(s2v * (float)mx), 0), 3);
            hv |= (unsigned int)a << (8 * c2);
        }
        *(unsigned short*)((char*)&a2w[g][0] + pp * 4 + cp * 2) = (unsigned short)hv;
    }
    __syncthreads();

    // ---- FC: 10 outputs x 49 dp4a ----------------------------------------
    if (u < 10) {
        int acc = 0;
        const int* wf = &g_wfpack[u * 49];
        #pragma unroll
        for (int j = 0; j < 12; j++) {
            int4 va = *(const int4*)&a2w[g][4 * j];
            acc = __dp4a(va.x, __ldg(wf + 4*j + 0), acc);
            acc = __dp4a(va.y, __ldg(wf + 4*j + 1), acc);
            acc = __dp4a(va.z, __ldg(wf + 4*j + 2), acc);
            acc = __dp4a(va.w, __ldg(wf + 4*j + 3), acc);
        }
        acc = __dp4a(a2w[g][48], __ldg(wf + 48), acc);
        out[(b0 + g) * 10 + u] = g_sf2 * (float)acc;
    }
}

extern "C" void kernel_launch(void* const* d_in, const int* in_sizes, int n_in,
                              void* d_out, int out_size) {
    const float* x  = (const float*)d_in[0];
    const float* w1 = (const float*)d_in[1];
    const float* w2 = (const float*)d_in[2];
    const float* wf = (const float*)d_in[3];
    float* out = (float*)d_out;
    const int B = in_sizes[0] / 784;

    prep_kernel<<<1, 256>>>(w1, w2, wf);
    net_kernel<<<B / 2, TPB>>>(x, out);
}

// round 11
// speedup vs baseline: 1.2037x; 1.2037x over previous
#include <cuda_runtime.h>
#include <math.h>

typedef unsigned long long ull;

// ---------------------------------------------------------------------------
// Net_47132971107101: fake-quant CNN forward
//   conv1 fp32: VERTICAL f32x2 pairing (pool rows in the two lanes), operands
//     prebuilt in parity-split smem -> conflict-free LDS.64, zero packing movs.
//     1 pooled output per thread, 392 flat tasks, 5 blocks/SM.
//   conv2 dp4a (2 channels/thread, 196 flat tasks) -> 2-bit a2
//   FC dp4a (20 flat tasks) -> out * 2*sf
// 2 images per 256-thread block.
// ---------------------------------------------------------------------------

__device__ __align__(16) ull g_w1d[48]; // ch*12 + ky*4 + kx (kx<3), (w,w) f32x2; pad=0
__device__ int   g_w2pack[36];          // 4 outch x 9 taps, 4 in-ch int8 per word
__device__ __align__(16) int g_wfpack[492]; // 10 outs x 49 words (+pad)
__device__ float g_s2v;
__device__ float g_sf2;

__global__ void prep_kernel(const float* __restrict__ w1,
                            const float* __restrict__ w2,
                            const float* __restrict__ wf) {
    __shared__ float red[256];
    const int t = threadIdx.x;

    float m = 0.f;
    for (int i = t; i < 36; i += 256) m = fmaxf(m, fabsf(w1[i]));
    red[t] = m; __syncthreads();
    for (int s = 128; s > 0; s >>= 1) { if (t < s) red[t] = fmaxf(red[t], red[t+s]); __syncthreads(); }
    const float s1 = red[0]; __syncthreads();

    m = 0.f;
    for (int i = t; i < 144; i += 256) m = fmaxf(m, fabsf(w2[i]));
    red[t] = m; __syncthreads();
    for (int s = 128; s > 0; s >>= 1) { if (t < s) red[t] = fmaxf(red[t], red[t+s]); __syncthreads(); }
    const float s2 = red[0]; __syncthreads();

    m = 0.f;
    for (int i = t; i < 1960; i += 256) m = fmaxf(m, fabsf(wf[i]));
    red[t] = m; __syncthreads();
    for (int s = 128; s > 0; s >>= 1) { if (t < s) red[t] = fmaxf(red[t], red[t+s]); __syncthreads(); }
    const float sf = red[0];

    // w1 padded: slot = ch*12 + ky*4 + kx, kx in 0..3 (kx==3 -> 0)
    if (t < 48) {
        const int ch = t / 12, r = t % 12, ky = r / 4, kx = r % 4;
        ull val = 0ull;
        if (kx < 3) {
            float q = fminf(fmaxf(rintf(w1[ch*9 + ky*3 + kx] / s1), -1.f), 1.f);
            float w = 0.5f * s1 * q;
            unsigned int u; memcpy(&u, &w, 4);
            val = ((ull)u << 32) | (ull)u;   // (w,w) f32x2 pair
        }
        g_w1d[t] = val;
    }
    if (t < 36) {
        const int o = t / 9, tap = t % 9;
        int pack = 0;
        #pragma unroll
        for (int i = 0; i < 4; i++) {
            float q = fminf(fmaxf(rintf(w2[o*36 + i*9 + tap] / s2), -1.f), 1.f);
            pack |= (((int)q) & 0xFF) << (8 * i);
        }
        g_w2pack[t] = pack;
    }
    for (int i = t; i < 490; i += 256) {
        const int o = i / 49, pp = i % 49;
        int pack = 0;
        #pragma unroll
        for (int j = 0; j < 4; j++) {
            float q = fminf(fmaxf(rintf(wf[o*196 + j*49 + pp] / sf), -1.f), 1.f);
            pack |= (((int)q) & 0xFF) << (8 * j);
        }
        g_wfpack[i] = pack;
    }
    if (t < 2) g_wfpack[490 + t] = 0;
    if (t == 0) { g_s2v = s2; g_sf2 = 2.f * sf; }
}

__device__ __forceinline__ void f2up(ull v, float& lo, float& hi) {
    asm("mov.b64 {%0,%1}, %2;" : "=f"(lo), "=f"(hi) : "l"(v));
}
__device__ __forceinline__ ull ffma2(ull a, ull b, ull c) {
    ull d; asm("fma.rn.f32x2 %0, %1, %2, %3;" : "=l"(d) : "l"(a), "l"(b), "l"(c)); return d;
}

#define TPB 256

__global__ void __launch_bounds__(TPB, 5)
net_kernel(const float* __restrict__ x, float* __restrict__ out) {
    // s_par[img][parity][r][j]: vertical pair (pad_row r, pad_row r+1) at padded
    // col 2j+parity. r in 0..28, j in 0..14. Zero-initialized = border padding.
    __shared__ __align__(16) ull s_par[2][2][29][15];   // 13920 B
    __shared__ __align__(16) int a1p[2][16 * 16];       // padded 14x14, 4ch bytes
    __shared__ __align__(16) int a2w[2][52];
    __shared__ __align__(16) ull s_w1[48];              // padded (w,w) weights

    const int t = threadIdx.x;
    const long long b0 = (long long)blockIdx.x * 2;

    // ---- phase 0: zero smem + weights ------------------------------------
    if (t < 48) s_w1[t] = g_w1d[t];
    for (int i = t; i < 2 * 2 * 29 * 15; i += TPB) ((ull*)s_par)[i] = 0ull;
    if (t < 120) {               // a1p borders: 60 cells per image
        int gi = t / 60, j = t % 60, y, c;
        if (j < 16)      { y = 0;          c = j; }
        else if (j < 32) { y = 15;         c = j - 16; }
        else if (j < 46) { y = j - 32 + 1; c = 0; }
        else             { y = j - 46 + 1; c = 15; }
        a1p[gi][y * 16 + c] = 0;
    }
    if (t < 6) a2w[t / 3][49 + (t % 3)] = 0;
    __syncthreads();

    // ---- phase 1: load x into vertical-pair parity arrays ----------------
    // value at image row y, col c (padded col c+1): appears as .hi of pair-row y
    // and .lo of pair-row y+1 in the (c+1)-parity array.
    for (int i = t; i < 392; i += TPB) {
        const int gi = i / 196, q = i % 196;
        float4 v = ((const float4*)(x + (b0 + gi) * 784))[q];
        const int p = q * 4, y = p / 28, c = p % 28;   // c even
        const int j0 = c / 2;
        // cols c..c+3 -> padded c+1(odd,j0), c+2(even,j0+1), c+3(odd,j0+1), c+4(even,j0+2)
        float* h;
        h = (float*)&s_par[gi][1][y][j0];         h[1] = v.x;
        h = (float*)&s_par[gi][1][y + 1][j0];     h[0] = v.x;
        h = (float*)&s_par[gi][0][y][j0 + 1];     h[1] = v.y;
        h = (float*)&s_par[gi][0][y + 1][j0 + 1]; h[0] = v.y;
        h = (float*)&s_par[gi][1][y][j0 + 1];     h[1] = v.z;
        h = (float*)&s_par[gi][1][y + 1][j0 + 1]; h[0] = v.z;
        h = (float*)&s_par[gi][0][y][j0 + 2];     h[1] = v.w;
        h = (float*)&s_par[gi][0][y + 1][j0 + 2]; h[0] = v.w;
    }
    __syncthreads();

    // ---- phase 2: conv1 + pool + quant; 1 pooled output per task ---------
    for (int task = t; task < 392; task += TPB) {
        const int gi = task / 196, v = task % 196;
        const int py = v / 14, px = v % 14;

        // V[ky][c] = vertical pair at pair-row 2py+ky, padded col 2px+c
        ull V[3][4];
        #pragma unroll
        for (int ky = 0; ky < 3; ky++) {
            const int r = 2 * py + ky;
            V[ky][0] = s_par[gi][0][r][px];
            V[ky][1] = s_par[gi][1][r][px];
            V[ky][2] = s_par[gi][0][r][px + 1];
            V[ky][3] = s_par[gi][1][r][px + 1];
        }

        int pk = 0;
        #pragma unroll
        for (int ch = 0; ch < 4; ch++) {
            ull a0 = 0ull, a1 = 0ull;     // lanes: (conv row 2py, conv row 2py+1)
            #pragma unroll
            for (int ky = 0; ky < 3; ky++) {
                const ulonglong2 w01 = *(const ulonglong2*)&s_w1[ch * 12 + ky * 4];
                const ull w2 = s_w1[ch * 12 + ky * 4 + 2];
                a0 = ffma2(V[ky][0], w01.x, a0);
                a0 = ffma2(V[ky][1], w01.y, a0);
                a0 = ffma2(V[ky][2], w2,    a0);
                a1 = ffma2(V[ky][1], w01.x, a1);
                a1 = ffma2(V[ky][2], w01.y, a1);
                a1 = ffma2(V[ky][3], w2,    a1);
            }
            float t0, bo0, t1, bo1;
            f2up(a0, t0, bo0); f2up(a1, t1, bo1);
            const float mx = fmaxf(fmaxf(t0, bo0), fmaxf(t1, bo1));
            const int a = min(max(__float2int_rn(mx), 0), 3);
            pk |= a << (8 * ch);
        }
        a1p[gi][(py + 1) * 16 + px + 1] = pk;
    }
    __syncthreads();

    // ---- phase 3: conv2 + pool + quant; (img, ch-pair, spatial) tasks ----
    if (t < 196) {
        const int gi = t / 98, v = t % 98;
        const int cp = v / 49, pp = v % 49;
        const int py = pp / 7, px = pp % 7;
        int q[4][4];
        #pragma unroll
        for (int r = 0; r < 4; r++) {
            int2 v0 = *(const int2*)&a1p[gi][(2 * py + r) * 16 + 2 * px];
            int2 v1 = *(const int2*)&a1p[gi][(2 * py + r) * 16 + 2 * px + 2];
            q[r][0] = v0.x; q[r][1] = v0.y; q[r][2] = v1.x; q[r][3] = v1.y;
        }
        const float s2v = g_s2v;
        unsigned int hv = 0;
        #pragma unroll
        for (int c2 = 0; c2 < 2; c2++) {
            const int ch = cp * 2 + c2;
            int wv[9];
            #pragma unroll
            for (int k = 0; k < 9; k++) wv[k] = __ldg(&g_w2pack[ch * 9 + k]);
            int mx = -2147483647;
            #pragma unroll
            for (int wy = 0; wy < 2; wy++)
                #pragma unroll
                for (int wx = 0; wx < 2; wx++) {
                    int acc = 0;
                    #pragma unroll
                    for (int ky = 0; ky < 3; ky++)
                        #pragma unroll
                        for (int kx = 0; kx < 3; kx++)
                            acc = __dp4a(q[wy + ky][wx + kx], wv[ky * 3 + kx], acc);
                    mx = max(mx, acc);
                }
            const int a = min(max(__float2int_rn(s2v * (float)mx), 0), 3);
            hv |= (unsigned int)a << (8 * c2);
        }
        *(unsigned short*)((char*)&a2w[gi][0] + pp * 4 + cp * 2) = (unsigned short)hv;
    }
    __syncthreads();

    // ---- phase 4: FC, 20 tasks -------------------------------------------
    if (t < 20) {
        const int gi = t / 10, o = t % 10;
        int acc = 0;
        const int* wf = &g_wfpack[o * 49];
        #pragma unroll
        for (int j = 0; j < 12; j++) {
            int4 va = *(const int4*)&a2w[gi][4 * j];
            acc = __dp4a(va.x, __ldg(wf + 4*j + 0), acc);
            acc = __dp4a(va.y, __ldg(wf + 4*j + 1), acc);
            acc = __dp4a(va.z, __ldg(wf + 4*j + 2), acc);
            acc = __dp4a(va.w, __ldg(wf + 4*j + 3), acc);
        }
        acc = __dp4a(a2w[gi][48], __ldg(wf + 48), acc);
        out[(b0 + gi) * 10 + o] = g_sf2 * (float)acc;
    }
}

extern "C" void kernel_launch(void* const* d_in, const int* in_sizes, int n_in,
                              void* d_out, int out_size) {
    const float* x  = (const float*)d_in[0];
    const float* w1 = (const float*)d_in[1];
    const float* w2 = (const float*)d_in[2];
    const float* wf = (const float*)d_in[3];
    float* out = (float*)d_out;
    const int B = in_sizes[0] / 784;

    prep_kernel<<<1, 256>>>(w1, w2, wf);
    net_kernel<<<B / 2, TPB>>>(x, out);
}